// round 3
// baseline (speedup 1.0000x reference)
#include <cuda_runtime.h>
#include <cstdint>

// ---------------- problem constants ----------------
#define B_ROWS   4096
#define HALF_DIM 1024
#define MID_DIM  4096
#define NH       4

// ---------------- scratch (device globals; no cudaMalloc allowed) ----------
__device__ float g_x2[(size_t)B_ROWS * HALF_DIM];                    // 16 MB
__device__ float g_h0[(size_t)B_ROWS * MID_DIM];                     // 64 MB
__device__ float g_h1[(size_t)B_ROWS * MID_DIM];                     // 64 MB
__device__ float g_wt[(size_t)HALF_DIM * MID_DIM +
                      (size_t)NH * MID_DIM * MID_DIM +
                      (size_t)MID_DIM * HALF_DIM];                   // 302 MB

// ---------------- helpers ----------------
__device__ __forceinline__ uint32_t smem_u32(const void* p) {
    uint32_t a;
    asm("{ .reg .u64 t; cvta.to.shared.u64 t, %1; cvt.u32.u64 %0, t; }"
        : "=r"(a) : "l"(p));
    return a;
}
__device__ __forceinline__ float f2tf32(float v) {   // round-to-nearest tf32
    uint32_t r; asm("cvt.rna.tf32.f32 %0, %1;" : "=r"(r) : "f"(v));
    return __uint_as_float(r);
}

#define CP_ASYNC16(dst_u32, src_ptr) \
    asm volatile("cp.async.cg.shared.global [%0], [%1], 16;" \
        :: "r"(dst_u32), "l"(src_ptr) : "memory")
#define CP_COMMIT() asm volatile("cp.async.commit_group;" ::: "memory")
#define CP_WAIT2()  asm volatile("cp.async.wait_group 2;"  ::: "memory")
#define CP_WAIT0()  asm volatile("cp.async.wait_group 0;"  ::: "memory")

__device__ __forceinline__ void mma_tf32(float* d, const float* a, const float* b) {
    asm volatile(
        "mma.sync.aligned.m16n8k8.row.col.f32.tf32.tf32.f32 "
        "{%0,%1,%2,%3}, {%4,%5,%6,%7}, {%8,%9}, {%0,%1,%2,%3};"
        : "+f"(d[0]), "+f"(d[1]), "+f"(d[2]), "+f"(d[3])
        : "r"(__float_as_uint(a[0])), "r"(__float_as_uint(a[1])),
          "r"(__float_as_uint(a[2])), "r"(__float_as_uint(a[3])),
          "r"(__float_as_uint(b[0])), "r"(__float_as_uint(b[1])));
}

// ---------------- prologue kernels ----------------
// x2[b,j] = rna_tf32(x[b, 2j+1]); log_det_J passthrough if out has room.
__global__ void prep_x2(const float* __restrict__ x, const float* __restrict__ ldj,
                        float* __restrict__ x2, float* __restrict__ yout, int write_ldj) {
    size_t i = (size_t)blockIdx.x * blockDim.x + threadIdx.x;
    float2 p = ((const float2*)x)[i];
    x2[i] = f2tf32(p.y);
    if (i == 0 && write_ldj) yout[(size_t)B_ROWS * 2 * HALF_DIM] = ldj[0];
}

// out[c, r] = rna_tf32(in[r, c]);  in is R x C (multiples of 32)
__global__ void transpose_tf32(const float* __restrict__ in, float* __restrict__ out,
                               int R, int C) {
    __shared__ float t[32][33];
    int c0 = blockIdx.x * 32, r0 = blockIdx.y * 32;
    t[threadIdx.y][threadIdx.x] = in[(size_t)(r0 + threadIdx.y) * C + c0 + threadIdx.x];
    __syncthreads();
    out[(size_t)(c0 + threadIdx.y) * R + r0 + threadIdx.x] = f2tf32(t[threadIdx.x][threadIdx.y]);
}

// ---------------- tf32 mma.sync GEMM ----------------
// C[M,N] = epi( A[M,K] @ Bt[N,K]^T + bias ), A and Bt K-major.
// Tile 128x128, KC=32, 4-stage cp.async pipeline, 256 threads (2x4 warps),
// warp tile 64x32 = 4x4 of m16n8k8.
// mode 0: C = rna_tf32(relu(acc+bias)), row stride MID_DIM
// mode 1: y[r,2n] = x[r,2n] + (acc+bias); y[r,2n+1] = x[r,2n+1]
#define TM 128
#define TN 128
#define KC 32
#define STAGES 4
#define PADK 36                               // floats per smem row (bank-safe, 16B mult)
#define TILE_WORDS (128 * PADK)               // 4608 floats per matrix
#define TILE_BYTES (TILE_WORDS * 4)           // 18432 B
#define GEMM_SMEM (STAGES * 2 * TILE_BYTES)   // 147456 B

__global__ void __launch_bounds__(256, 1)
gemm_tf32(const float* __restrict__ A, const float* __restrict__ Bt,
          const float* __restrict__ bias, float* __restrict__ C,
          const float* __restrict__ xin, float* __restrict__ yout,
          int K, int n_chunks, int mode) {
    extern __shared__ float smem[];
    const uint32_t sbase = smem_u32(smem);
    const int tid  = threadIdx.x;
    const int wid  = tid >> 5;
    const int lane = tid & 31;
    const int wm   = wid >> 2;          // 0..1  (M warps)
    const int wn   = wid & 3;           // 0..3  (N warps)
    const int gid  = lane >> 2;         // 0..7
    const int tg   = lane & 3;          // 0..3
    const int m0   = blockIdx.y * TM;
    const int n0   = blockIdx.x * TN;

    const float* ag0 = A  + (size_t)m0 * K;
    const float* bg0 = Bt + (size_t)n0 * K;

    // ---- producer: issue one stage's cp.asyncs ----
    auto load_stage = [&](int s, int c) {
        const float* ag = ag0 + (size_t)c * KC;
        const float* bg = bg0 + (size_t)c * KC;
        const uint32_t sa = sbase + (uint32_t)s * 2u * TILE_BYTES;
        const uint32_t sb = sa + TILE_BYTES;
        #pragma unroll
        for (int i = 0; i < 4; i++) {
            int id  = tid + 256 * i;
            int row = id >> 3, col = id & 7;
            uint32_t off = (uint32_t)(row * PADK + col * 4) * 4u;
            CP_ASYNC16(sa + off, ag + (size_t)row * K + col * 4);
            CP_ASYNC16(sb + off, bg + (size_t)row * K + col * 4);
        }
        CP_COMMIT();
    };

    float acc[4][4][4];
    #pragma unroll
    for (int i = 0; i < 4; i++)
        #pragma unroll
        for (int j = 0; j < 4; j++)
            #pragma unroll
            for (int v = 0; v < 4; v++) acc[i][j][v] = 0.f;

    // prologue: fill STAGES-1 stages
    #pragma unroll
    for (int s = 0; s < STAGES - 1; s++) load_stage(s, s);

    for (int c = 0; c < n_chunks; c++) {
        CP_WAIT2();
        __syncthreads();
        const int s = c & (STAGES - 1);
        const float* As = smem + (size_t)s * 2 * TILE_WORDS;
        const float* Bs = As + TILE_WORDS;

        #pragma unroll
        for (int ks = 0; ks < 4; ks++) {
            const int k = ks * 8;
            float af[4][4], bf[4][2];
            #pragma unroll
            for (int mt = 0; mt < 4; mt++) {
                int r = wm * 64 + mt * 16 + gid;
                af[mt][0] = As[r * PADK + k + tg];
                af[mt][1] = As[(r + 8) * PADK + k + tg];
                af[mt][2] = As[r * PADK + k + tg + 4];
                af[mt][3] = As[(r + 8) * PADK + k + tg + 4];
            }
            #pragma unroll
            for (int nt = 0; nt < 4; nt++) {
                int n = wn * 32 + nt * 8 + gid;
                bf[nt][0] = Bs[n * PADK + k + tg];
                bf[nt][1] = Bs[n * PADK + k + tg + 4];
            }
            #pragma unroll
            for (int mt = 0; mt < 4; mt++)
                #pragma unroll
                for (int nt = 0; nt < 4; nt++)
                    mma_tf32(acc[mt][nt], af[mt], bf[nt]);
        }
        __syncthreads();
        if (c + STAGES - 1 < n_chunks)
            load_stage((c + STAGES - 1) & (STAGES - 1), c + STAGES - 1);
    }
    CP_WAIT0();

    // ---- epilogue ----
    if (mode == 0) {
        #pragma unroll
        for (int mt = 0; mt < 4; mt++) {
            int r = m0 + wm * 64 + mt * 16 + gid;
            #pragma unroll
            for (int nt = 0; nt < 4; nt++) {
                int cb = n0 + wn * 32 + nt * 8 + 2 * tg;
                float b0 = bias[cb], b1 = bias[cb + 1];
                float2 v0, v1;
                v0.x = f2tf32(fmaxf(acc[mt][nt][0] + b0, 0.f));
                v0.y = f2tf32(fmaxf(acc[mt][nt][1] + b1, 0.f));
                v1.x = f2tf32(fmaxf(acc[mt][nt][2] + b0, 0.f));
                v1.y = f2tf32(fmaxf(acc[mt][nt][3] + b1, 0.f));
                *(float2*)(C + (size_t)r * MID_DIM + cb)       = v0;
                *(float2*)(C + (size_t)(r + 8) * MID_DIM + cb) = v1;
            }
        }
    } else {
        #pragma unroll
        for (int mt = 0; mt < 4; mt++) {
            int r = m0 + wm * 64 + mt * 16 + gid;
            #pragma unroll
            for (int nt = 0; nt < 4; nt++) {
                int cb = n0 + wn * 32 + nt * 8 + 2 * tg;    // even
                float b0 = bias[cb], b1 = bias[cb + 1];
                {
                    const float4 xv = *(const float4*)(xin + (size_t)r * 2 * HALF_DIM + 2 * cb);
                    float4 yv;
                    yv.x = xv.x + acc[mt][nt][0] + b0;
                    yv.y = xv.y;
                    yv.z = xv.z + acc[mt][nt][1] + b1;
                    yv.w = xv.w;
                    *(float4*)(yout + (size_t)r * 2 * HALF_DIM + 2 * cb) = yv;
                }
                {
                    const float4 xv = *(const float4*)(xin + (size_t)(r + 8) * 2 * HALF_DIM + 2 * cb);
                    float4 yv;
                    yv.x = xv.x + acc[mt][nt][2] + b0;
                    yv.y = xv.y;
                    yv.z = xv.z + acc[mt][nt][3] + b1;
                    yv.w = xv.w;
                    *(float4*)(yout + (size_t)(r + 8) * 2 * HALF_DIM + 2 * cb) = yv;
                }
            }
        }
    }
}

// ---------------- host ----------------
extern "C" void kernel_launch(void* const* d_in, const int* in_sizes, int n_in,
                              void* d_out, int out_size) {
    const float* x     = (const float*)d_in[0];
    const float* ldj   = (const float*)d_in[1];
    const float* W_in  = (const float*)d_in[2];
    const float* b_in  = (const float*)d_in[3];
    const float* W_h   = (const float*)d_in[4];
    const float* b_h   = (const float*)d_in[5];
    const float* W_out = (const float*)d_in[6];
    const float* b_out = (const float*)d_in[7];
    float* y = (float*)d_out;
    (void)in_sizes; (void)n_in;

    float *px2, *ph0, *ph1, *pwt;
    cudaGetSymbolAddress((void**)&px2, g_x2);
    cudaGetSymbolAddress((void**)&ph0, g_h0);
    cudaGetSymbolAddress((void**)&ph1, g_h1);
    cudaGetSymbolAddress((void**)&pwt, g_wt);

    cudaFuncSetAttribute(gemm_tf32, cudaFuncAttributeMaxDynamicSharedMemorySize, GEMM_SMEM);

    const size_t OFF_WIN  = 0;
    const size_t OFF_WH   = (size_t)HALF_DIM * MID_DIM;
    const size_t OFF_WOUT = OFF_WH + (size_t)NH * MID_DIM * MID_DIM;

    int write_ldj = (out_size > B_ROWS * 2 * HALF_DIM) ? 1 : 0;
    prep_x2<<<(B_ROWS * HALF_DIM) / 256, 256>>>(x, ldj, px2, y, write_ldj);

    dim3 tb(32, 32);
    transpose_tf32<<<dim3(MID_DIM / 32, HALF_DIM / 32), tb>>>(W_in, pwt + OFF_WIN, HALF_DIM, MID_DIM);
    for (int i = 0; i < NH; i++)
        transpose_tf32<<<dim3(MID_DIM / 32, MID_DIM / 32), tb>>>(
            W_h + (size_t)i * MID_DIM * MID_DIM,
            pwt + OFF_WH + (size_t)i * MID_DIM * MID_DIM, MID_DIM, MID_DIM);
    transpose_tf32<<<dim3(HALF_DIM / 32, MID_DIM / 32), tb>>>(W_out, pwt + OFF_WOUT, MID_DIM, HALF_DIM);

    // L1: h0 = relu(x2 @ W_in + b_in)   [M=4096, N=4096, K=1024]
    gemm_tf32<<<dim3(MID_DIM / TN, B_ROWS / TM), 256, GEMM_SMEM>>>(
        px2, pwt + OFF_WIN, b_in, ph0, nullptr, nullptr, HALF_DIM, HALF_DIM / KC, 0);

    // hidden layers [4096,4096,4096]
    for (int i = 0; i < NH; i++) {
        const float* Ain = (i % 2 == 0) ? ph0 : ph1;
        float* Cc        = (i % 2 == 0) ? ph1 : ph0;
        gemm_tf32<<<dim3(MID_DIM / TN, B_ROWS / TM), 256, GEMM_SMEM>>>(
            Ain, pwt + OFF_WH + (size_t)i * MID_DIM * MID_DIM,
            b_h + (size_t)i * MID_DIM, Cc, nullptr, nullptr, MID_DIM, MID_DIM / KC, 0);
    }

    // L6: y = interleave(x1 + h @ W_out + b_out, x2)   [M=4096, N=1024, K=4096]
    gemm_tf32<<<dim3(HALF_DIM / TN, B_ROWS / TM), 256, GEMM_SMEM>>>(
        ph0, pwt + OFF_WOUT, b_out, nullptr, x, y, MID_DIM, MID_DIM / KC, 1);
}

// round 4
// speedup vs baseline: 2.2722x; 2.2722x over previous
#include <cuda_runtime.h>
#include <cuda_bf16.h>
#include <cstdint>

// ---------------- problem constants ----------------
#define B_ROWS   4096
#define HALF_DIM 1024
#define MID_DIM  4096
#define NH       4

// ---------------- scratch (device globals; no cudaMalloc allowed) ----------
__device__ __nv_bfloat16 g_x2[(size_t)B_ROWS * HALF_DIM];            //  8 MB
__device__ __nv_bfloat16 g_h0[(size_t)B_ROWS * MID_DIM];             // 32 MB
__device__ __nv_bfloat16 g_h1[(size_t)B_ROWS * MID_DIM];             // 32 MB
__device__ __nv_bfloat16 g_wt[(size_t)HALF_DIM * MID_DIM +
                              (size_t)NH * MID_DIM * MID_DIM +
                              (size_t)MID_DIM * HALF_DIM];           // 151 MB

// ---------------- helpers ----------------
__device__ __forceinline__ uint32_t smem_u32(const void* p) {
    uint32_t a;
    asm("{ .reg .u64 t; cvta.to.shared.u64 t, %1; cvt.u32.u64 %0, t; }"
        : "=r"(a) : "l"(p));
    return a;
}

#define CP_ASYNC16(dst_u32, src_ptr) \
    asm volatile("cp.async.cg.shared.global [%0], [%1], 16;" \
        :: "r"(dst_u32), "l"(src_ptr) : "memory")
#define CP_COMMIT() asm volatile("cp.async.commit_group;" ::: "memory")
#define CP_WAIT1()  asm volatile("cp.async.wait_group 1;"  ::: "memory")
#define CP_WAIT0()  asm volatile("cp.async.wait_group 0;"  ::: "memory")

#define LDSM_X4(r0, r1, r2, r3, addr) \
    asm volatile("ldmatrix.sync.aligned.m8n8.x4.shared.b16 {%0,%1,%2,%3}, [%4];" \
        : "=r"(r0), "=r"(r1), "=r"(r2), "=r"(r3) : "r"(addr))

__device__ __forceinline__ void mma_bf16(float* d, const uint32_t* a, const uint32_t* b) {
    asm volatile(
        "mma.sync.aligned.m16n8k16.row.col.f32.bf16.bf16.f32 "
        "{%0,%1,%2,%3}, {%4,%5,%6,%7}, {%8,%9}, {%0,%1,%2,%3};"
        : "+f"(d[0]), "+f"(d[1]), "+f"(d[2]), "+f"(d[3])
        : "r"(a[0]), "r"(a[1]), "r"(a[2]), "r"(a[3]), "r"(b[0]), "r"(b[1]));
}

// ---------------- prologue kernels ----------------
// x2[b,j] = bf16(x[b, 2j+1]); log_det_J passthrough if out has room.
__global__ void prep_x2(const float* __restrict__ x, const float* __restrict__ ldj,
                        __nv_bfloat16* __restrict__ x2, float* __restrict__ yout,
                        int write_ldj) {
    size_t i = (size_t)blockIdx.x * blockDim.x + threadIdx.x;
    float2 p = ((const float2*)x)[i];
    x2[i] = __float2bfloat16(p.y);
    if (i == 0 && write_ldj) yout[(size_t)B_ROWS * 2 * HALF_DIM] = ldj[0];
}

// out[c, r] = bf16(in[r, c]); in is R x C fp32 (multiples of 32)
__global__ void transpose_bf16(const float* __restrict__ in, __nv_bfloat16* __restrict__ out,
                               int R, int C) {
    __shared__ float t[32][33];
    int c0 = blockIdx.x * 32, r0 = blockIdx.y * 32;
    t[threadIdx.y][threadIdx.x] = in[(size_t)(r0 + threadIdx.y) * C + c0 + threadIdx.x];
    __syncthreads();
    out[(size_t)(c0 + threadIdx.y) * R + r0 + threadIdx.x] =
        __float2bfloat16(t[threadIdx.x][threadIdx.y]);
}

// ---------------- bf16 mma.sync GEMM ----------------
// C[M,N] = epi( A[M,K] @ Bt[N,K]^T + bias ), A and Bt K-major bf16.
// Tile 128x128, KC=64 halves, 3-stage cp.async pipeline, 128 threads (2x2 warps),
// warp tile 64x64 = 4(m16) x 8(n8) of m16n8k16; ldmatrix fragment loads.
// mode 0: C = bf16(relu(acc+bias)), row stride MID_DIM
// mode 1: y[r,2n] = x[r,2n] + (acc+bias); y[r,2n+1] = x[r,2n+1]
#define TM 128
#define TN 128
#define KC 64
#define STAGES 3
#define ROWH 72                                    // halves per padded smem row
#define ROWB (ROWH * 2)                            // 144 B
#define TILE_BYTES (128 * ROWB)                    // 18432
#define STG_BYTES  (2 * TILE_BYTES)                // 36864
#define GEMM_SMEM  (STAGES * STG_BYTES)            // 110592

__global__ void __launch_bounds__(128, 2)
gemm_bf16(const __nv_bfloat16* __restrict__ A, const __nv_bfloat16* __restrict__ Bt,
          const float* __restrict__ bias, __nv_bfloat16* __restrict__ C,
          const float* __restrict__ xin, float* __restrict__ yout,
          int K, int n_chunks, int mode) {
    extern __shared__ char smem[];
    const uint32_t sbase = smem_u32(smem);
    const int tid  = threadIdx.x;
    const int wid  = tid >> 5;
    const int lane = tid & 31;
    const int wm   = wid >> 1;              // 0..1
    const int wn   = wid & 1;               // 0..1
    const int gid  = lane >> 2;             // 0..7
    const int tg   = lane & 3;              // 0..3
    const int m0   = blockIdx.y * TM;
    const int n0   = blockIdx.x * TN;

    const __nv_bfloat16* ag0 = A  + (size_t)m0 * K;
    const __nv_bfloat16* bg0 = Bt + (size_t)n0 * K;

    // per-lane ldmatrix base offsets (bytes within a tile)
    const uint32_t a_off = (uint32_t)((wm * 64 + (lane & 15)) * ROWB + (lane >> 4) * 16);
    const uint32_t b_off = (uint32_t)((wn * 64 + (lane & 7) + ((lane >> 4) << 3)) * ROWB +
                                      ((lane >> 3) & 1) * 16);

    auto load_stage = [&](int s, int c) {
        const __nv_bfloat16* ag = ag0 + (size_t)c * KC;
        const __nv_bfloat16* bg = bg0 + (size_t)c * KC;
        const uint32_t sa = sbase + (uint32_t)s * STG_BYTES;
        const uint32_t sb = sa + TILE_BYTES;
        #pragma unroll
        for (int i = 0; i < 8; i++) {
            int id  = tid + 128 * i;
            int row = id >> 3, col = id & 7;
            uint32_t off = (uint32_t)(row * ROWB + col * 16);
            CP_ASYNC16(sa + off, ag + (size_t)row * K + col * 8);
            CP_ASYNC16(sb + off, bg + (size_t)row * K + col * 8);
        }
        CP_COMMIT();
    };

    float acc[4][8][4];
    #pragma unroll
    for (int i = 0; i < 4; i++)
        #pragma unroll
        for (int j = 0; j < 8; j++)
            #pragma unroll
            for (int v = 0; v < 4; v++) acc[i][j][v] = 0.f;

    load_stage(0, 0);
    load_stage(1, 1);

    int s = 0;
    for (int c = 0; c < n_chunks; c++) {
        CP_WAIT1();
        __syncthreads();
        if (c + 2 < n_chunks) {
            int s2 = s + 2; if (s2 >= STAGES) s2 -= STAGES;
            load_stage(s2, c + 2);
        }
        const uint32_t sa = sbase + (uint32_t)s * STG_BYTES;
        const uint32_t sb = sa + TILE_BYTES;

        #pragma unroll
        for (int ks = 0; ks < KC / 16; ks++) {
            uint32_t af[4][4], bf[4][4];
            #pragma unroll
            for (int mt = 0; mt < 4; mt++)
                LDSM_X4(af[mt][0], af[mt][1], af[mt][2], af[mt][3],
                        sa + a_off + (uint32_t)(mt * 16 * ROWB + ks * 32));
            #pragma unroll
            for (int np = 0; np < 4; np++)
                LDSM_X4(bf[np][0], bf[np][1], bf[np][2], bf[np][3],
                        sb + b_off + (uint32_t)(np * 16 * ROWB + ks * 32));
            #pragma unroll
            for (int mt = 0; mt < 4; mt++)
                #pragma unroll
                for (int nt = 0; nt < 8; nt++)
                    mma_bf16(acc[mt][nt], af[mt], &bf[nt >> 1][(nt & 1) * 2]);
        }
        if (++s == STAGES) s = 0;
    }
    CP_WAIT0();

    // ---- epilogue ----
    if (mode == 0) {
        #pragma unroll
        for (int mt = 0; mt < 4; mt++) {
            int r = m0 + wm * 64 + mt * 16 + gid;
            #pragma unroll
            for (int nt = 0; nt < 8; nt++) {
                int cb = n0 + wn * 64 + nt * 8 + 2 * tg;
                float b0 = bias[cb], b1 = bias[cb + 1];
                __nv_bfloat162 v0 = __floats2bfloat162_rn(
                    fmaxf(acc[mt][nt][0] + b0, 0.f), fmaxf(acc[mt][nt][1] + b1, 0.f));
                __nv_bfloat162 v1 = __floats2bfloat162_rn(
                    fmaxf(acc[mt][nt][2] + b0, 0.f), fmaxf(acc[mt][nt][3] + b1, 0.f));
                *(__nv_bfloat162*)(C + (size_t)r * MID_DIM + cb)       = v0;
                *(__nv_bfloat162*)(C + (size_t)(r + 8) * MID_DIM + cb) = v1;
            }
        }
    } else {
        #pragma unroll
        for (int mt = 0; mt < 4; mt++) {
            int r = m0 + wm * 64 + mt * 16 + gid;
            #pragma unroll
            for (int nt = 0; nt < 8; nt++) {
                int cb = n0 + wn * 64 + nt * 8 + 2 * tg;
                float b0 = bias[cb], b1 = bias[cb + 1];
                {
                    const float4 xv = *(const float4*)(xin + (size_t)r * 2 * HALF_DIM + 2 * cb);
                    float4 yv;
                    yv.x = xv.x + acc[mt][nt][0] + b0;
                    yv.y = xv.y;
                    yv.z = xv.z + acc[mt][nt][1] + b1;
                    yv.w = xv.w;
                    *(float4*)(yout + (size_t)r * 2 * HALF_DIM + 2 * cb) = yv;
                }
                {
                    const float4 xv = *(const float4*)(xin + (size_t)(r + 8) * 2 * HALF_DIM + 2 * cb);
                    float4 yv;
                    yv.x = xv.x + acc[mt][nt][2] + b0;
                    yv.y = xv.y;
                    yv.z = xv.z + acc[mt][nt][3] + b1;
                    yv.w = xv.w;
                    *(float4*)(yout + (size_t)(r + 8) * 2 * HALF_DIM + 2 * cb) = yv;
                }
            }
        }
    }
}

// ---------------- host ----------------
extern "C" void kernel_launch(void* const* d_in, const int* in_sizes, int n_in,
                              void* d_out, int out_size) {
    const float* x     = (const float*)d_in[0];
    const float* ldj   = (const float*)d_in[1];
    const float* W_in  = (const float*)d_in[2];
    const float* b_in  = (const float*)d_in[3];
    const float* W_h   = (const float*)d_in[4];
    const float* b_h   = (const float*)d_in[5];
    const float* W_out = (const float*)d_in[6];
    const float* b_out = (const float*)d_in[7];
    float* y = (float*)d_out;
    (void)in_sizes; (void)n_in;

    __nv_bfloat16 *px2, *ph0, *ph1, *pwt;
    cudaGetSymbolAddress((void**)&px2, g_x2);
    cudaGetSymbolAddress((void**)&ph0, g_h0);
    cudaGetSymbolAddress((void**)&ph1, g_h1);
    cudaGetSymbolAddress((void**)&pwt, g_wt);

    cudaFuncSetAttribute(gemm_bf16, cudaFuncAttributeMaxDynamicSharedMemorySize, GEMM_SMEM);

    const size_t OFF_WIN  = 0;
    const size_t OFF_WH   = (size_t)HALF_DIM * MID_DIM;
    const size_t OFF_WOUT = OFF_WH + (size_t)NH * MID_DIM * MID_DIM;

    int write_ldj = (out_size > B_ROWS * 2 * HALF_DIM) ? 1 : 0;
    prep_x2<<<(B_ROWS * HALF_DIM) / 256, 256>>>(x, ldj, px2, y, write_ldj);

    dim3 tb(32, 32);
    transpose_bf16<<<dim3(MID_DIM / 32, HALF_DIM / 32), tb>>>(W_in, pwt + OFF_WIN, HALF_DIM, MID_DIM);
    for (int i = 0; i < NH; i++)
        transpose_bf16<<<dim3(MID_DIM / 32, MID_DIM / 32), tb>>>(
            W_h + (size_t)i * MID_DIM * MID_DIM,
            pwt + OFF_WH + (size_t)i * MID_DIM * MID_DIM, MID_DIM, MID_DIM);
    transpose_bf16<<<dim3(HALF_DIM / 32, MID_DIM / 32), tb>>>(W_out, pwt + OFF_WOUT, MID_DIM, HALF_DIM);

    // L1: h0 = relu(x2 @ W_in + b_in)   [M=4096, N=4096, K=1024]
    gemm_bf16<<<dim3(MID_DIM / TN, B_ROWS / TM), 128, GEMM_SMEM>>>(
        px2, pwt + OFF_WIN, b_in, ph0, nullptr, nullptr, HALF_DIM, HALF_DIM / KC, 0);

    // hidden layers [4096,4096,4096]
    for (int i = 0; i < NH; i++) {
        const __nv_bfloat16* Ain = (i % 2 == 0) ? ph0 : ph1;
        __nv_bfloat16* Cc        = (i % 2 == 0) ? ph1 : ph0;
        gemm_bf16<<<dim3(MID_DIM / TN, B_ROWS / TM), 128, GEMM_SMEM>>>(
            Ain, pwt + OFF_WH + (size_t)i * MID_DIM * MID_DIM,
            b_h + (size_t)i * MID_DIM, Cc, nullptr, nullptr, MID_DIM, MID_DIM / KC, 0);
    }

    // L6: y = interleave(x1 + h @ W_out + b_out, x2)   [M=4096, N=1024, K=4096]
    gemm_bf16<<<dim3(HALF_DIM / TN, B_ROWS / TM), 128, GEMM_SMEM>>>(
        ph0, pwt + OFF_WOUT, b_out, nullptr, x, y, MID_DIM, MID_DIM / KC, 1);
}

// round 5
// speedup vs baseline: 2.4495x; 1.0780x over previous
#include <cuda_runtime.h>
#include <cuda_bf16.h>
#include <cstdint>

// ---------------- problem constants ----------------
#define B_ROWS   4096
#define HALF_DIM 1024
#define MID_DIM  4096
#define NH       4

// ---------------- scratch (device globals; no cudaMalloc allowed) ----------
__device__ __nv_bfloat16 g_x2[(size_t)B_ROWS * HALF_DIM];            //  8 MB
__device__ __nv_bfloat16 g_h0[(size_t)B_ROWS * MID_DIM];             // 32 MB
__device__ __nv_bfloat16 g_h1[(size_t)B_ROWS * MID_DIM];             // 32 MB
__device__ __nv_bfloat16 g_wt[(size_t)HALF_DIM * MID_DIM +
                              (size_t)NH * MID_DIM * MID_DIM +
                              (size_t)MID_DIM * HALF_DIM];           // 151 MB (original [K,N] layout)

// ---------------- helpers ----------------
__device__ __forceinline__ uint32_t smem_u32(const void* p) {
    uint32_t a;
    asm("{ .reg .u64 t; cvta.to.shared.u64 t, %1; cvt.u32.u64 %0, t; }"
        : "=r"(a) : "l"(p));
    return a;
}

#define CP_ASYNC16(dst_u32, src_ptr) \
    asm volatile("cp.async.cg.shared.global [%0], [%1], 16;" \
        :: "r"(dst_u32), "l"(src_ptr) : "memory")
#define CP_COMMIT() asm volatile("cp.async.commit_group;" ::: "memory")
#define CP_WAIT1()  asm volatile("cp.async.wait_group 1;"  ::: "memory")
#define CP_WAIT0()  asm volatile("cp.async.wait_group 0;"  ::: "memory")

#define LDSM_X4(r0, r1, r2, r3, addr) \
    asm volatile("ldmatrix.sync.aligned.m8n8.x4.shared.b16 {%0,%1,%2,%3}, [%4];" \
        : "=r"(r0), "=r"(r1), "=r"(r2), "=r"(r3) : "r"(addr))

#define LDSM_X4_T(r0, r1, r2, r3, addr) \
    asm volatile("ldmatrix.sync.aligned.m8n8.x4.trans.shared.b16 {%0,%1,%2,%3}, [%4];" \
        : "=r"(r0), "=r"(r1), "=r"(r2), "=r"(r3) : "r"(addr))

__device__ __forceinline__ void mma_bf16(float* d, const uint32_t* a, const uint32_t* b) {
    asm volatile(
        "mma.sync.aligned.m16n8k16.row.col.f32.bf16.bf16.f32 "
        "{%0,%1,%2,%3}, {%4,%5,%6,%7}, {%8,%9}, {%0,%1,%2,%3};"
        : "+f"(d[0]), "+f"(d[1]), "+f"(d[2]), "+f"(d[3])
        : "r"(a[0]), "r"(a[1]), "r"(a[2]), "r"(a[3]), "r"(b[0]), "r"(b[1]));
}

// ---------------- prologue kernels ----------------
// x2[b,j] = bf16(x[b, 2j+1]); log_det_J passthrough if out has room.
__global__ void prep_x2(const float* __restrict__ x, const float* __restrict__ ldj,
                        __nv_bfloat16* __restrict__ x2, float* __restrict__ yout,
                        int write_ldj) {
    size_t i = (size_t)blockIdx.x * blockDim.x + threadIdx.x;
    float2 p = ((const float2*)x)[i];
    x2[i] = __float2bfloat16(p.y);
    if (i == 0 && write_ldj) yout[(size_t)B_ROWS * 2 * HALF_DIM] = ldj[0];
}

// streaming fp32 -> bf16 convert (layout-preserving), 4 elems/thread
__global__ void convert_bf16(const float* __restrict__ in, __nv_bfloat16* __restrict__ out) {
    size_t i = (size_t)blockIdx.x * blockDim.x + threadIdx.x;
    float4 v = ((const float4*)in)[i];
    __nv_bfloat162* o = (__nv_bfloat162*)out + 2 * i;
    o[0] = __floats2bfloat162_rn(v.x, v.y);
    o[1] = __floats2bfloat162_rn(v.z, v.w);
}

// ---------------- bf16 mma.sync GEMM ----------------
// C[M,N] = epi( A[M,K] @ W[K,N] + bias ); A K-major bf16, W [K,N] row-major bf16.
// Tile 128x128, KC=64, 3-stage cp.async pipeline, 128 threads (2x2 warps),
// warp tile 64x64; A via ldmatrix, W via ldmatrix.trans (no pre-transpose).
// mode 0: C = bf16(relu(acc+bias)), row stride MID_DIM
// mode 1: y[r,2n] = x[r,2n] + (acc+bias); y[r,2n+1] = x[r,2n+1]
#define TM 128
#define TN 128
#define KC 64
#define STAGES 3
#define AROWB 144                                  // 64 halves + 16B pad
#define BROWB 272                                  // 128 halves + 16B pad
#define A_TILE (128 * AROWB)                       // 18432
#define B_TILE (KC * BROWB)                        // 17408
#define STG_BYTES (A_TILE + B_TILE)                // 35840
#define GEMM_SMEM (STAGES * STG_BYTES)             // 107520

__global__ void __launch_bounds__(128, 2)
gemm_bf16(const __nv_bfloat16* __restrict__ A, const __nv_bfloat16* __restrict__ W,
          const float* __restrict__ bias, __nv_bfloat16* __restrict__ C,
          const float* __restrict__ xin, float* __restrict__ yout,
          int K, int N, int n_chunks, int mode) {
    extern __shared__ char smem[];
    const uint32_t sbase = smem_u32(smem);
    const int tid  = threadIdx.x;
    const int wid  = tid >> 5;
    const int lane = tid & 31;
    const int wm   = wid >> 1;              // 0..1
    const int wn   = wid & 1;               // 0..1
    const int gid  = lane >> 2;             // 0..7
    const int tg   = lane & 3;              // 0..3
    const int m0   = blockIdx.y * TM;
    const int n0   = blockIdx.x * TN;

    const __nv_bfloat16* ag0 = A + (size_t)m0 * K;
    const __nv_bfloat16* bg0 = W + n0;

    // ldmatrix lane offsets
    const uint32_t a_off = (uint32_t)((wm * 64 + (lane & 15)) * AROWB + (lane >> 4) * 16);
    // trans-B: lane groups -> (k0-7,nlo),(k8-15,nlo),(k0-7,nhi),(k8-15,nhi)
    const int krow = (lane & 7) | (((lane >> 3) & 1) << 3);
    const uint32_t b_off = (uint32_t)(krow * BROWB + wn * 128 + (lane >> 4) * 16);

    auto load_stage = [&](int s, int c) {
        const __nv_bfloat16* ag = ag0 + (size_t)c * KC;
        const __nv_bfloat16* bg = bg0 + (size_t)c * KC * N;
        const uint32_t sa = sbase + (uint32_t)s * STG_BYTES;
        const uint32_t sb = sa + A_TILE;
        #pragma unroll
        for (int i = 0; i < 8; i++) {                 // A: 128 rows x 8 x 16B
            int id  = tid + 128 * i;
            int row = id >> 3, col = id & 7;
            CP_ASYNC16(sa + (uint32_t)(row * AROWB + col * 16),
                       ag + (size_t)row * K + col * 8);
        }
        #pragma unroll
        for (int i = 0; i < 8; i++) {                 // B: 64 rows x 16 x 16B
            int id  = tid + 128 * i;
            int row = id >> 4, col = id & 15;
            CP_ASYNC16(sb + (uint32_t)(row * BROWB + col * 16),
                       bg + (size_t)row * N + col * 8);
        }
        CP_COMMIT();
    };

    float acc[4][8][4];
    #pragma unroll
    for (int i = 0; i < 4; i++)
        #pragma unroll
        for (int j = 0; j < 8; j++)
            #pragma unroll
            for (int v = 0; v < 4; v++) acc[i][j][v] = 0.f;

    load_stage(0, 0);
    load_stage(1, 1);

    int s = 0;
    for (int c = 0; c < n_chunks; c++) {
        CP_WAIT1();
        __syncthreads();
        if (c + 2 < n_chunks) {
            int s2 = s + 2; if (s2 >= STAGES) s2 -= STAGES;
            load_stage(s2, c + 2);
        }
        const uint32_t sa = sbase + (uint32_t)s * STG_BYTES;
        const uint32_t sb = sa + A_TILE;

        #pragma unroll
        for (int ks = 0; ks < KC / 16; ks++) {
            uint32_t af[4][4], bf[4][4];
            #pragma unroll
            for (int mt = 0; mt < 4; mt++)
                LDSM_X4(af[mt][0], af[mt][1], af[mt][2], af[mt][3],
                        sa + a_off + (uint32_t)(mt * 16 * AROWB + ks * 32));
            #pragma unroll
            for (int np = 0; np < 4; np++)
                LDSM_X4_T(bf[np][0], bf[np][1], bf[np][2], bf[np][3],
                          sb + b_off + (uint32_t)(ks * 16 * BROWB + np * 32));
            #pragma unroll
            for (int mt = 0; mt < 4; mt++)
                #pragma unroll
                for (int nt = 0; nt < 8; nt++)
                    mma_bf16(acc[mt][nt], af[mt], &bf[nt >> 1][(nt & 1) * 2]);
        }
        if (++s == STAGES) s = 0;
    }
    CP_WAIT0();

    // ---- epilogue ----
    if (mode == 0) {
        #pragma unroll
        for (int mt = 0; mt < 4; mt++) {
            int r = m0 + wm * 64 + mt * 16 + gid;
            #pragma unroll
            for (int nt = 0; nt < 8; nt++) {
                int cb = n0 + wn * 64 + nt * 8 + 2 * tg;
                float b0 = bias[cb], b1 = bias[cb + 1];
                __nv_bfloat162 v0 = __floats2bfloat162_rn(
                    fmaxf(acc[mt][nt][0] + b0, 0.f), fmaxf(acc[mt][nt][1] + b1, 0.f));
                __nv_bfloat162 v1 = __floats2bfloat162_rn(
                    fmaxf(acc[mt][nt][2] + b0, 0.f), fmaxf(acc[mt][nt][3] + b1, 0.f));
                *(__nv_bfloat162*)(C + (size_t)r * MID_DIM + cb)       = v0;
                *(__nv_bfloat162*)(C + (size_t)(r + 8) * MID_DIM + cb) = v1;
            }
        }
    } else {
        #pragma unroll
        for (int mt = 0; mt < 4; mt++) {
            int r = m0 + wm * 64 + mt * 16 + gid;
            #pragma unroll
            for (int nt = 0; nt < 8; nt++) {
                int cb = n0 + wn * 64 + nt * 8 + 2 * tg;
                float b0 = bias[cb], b1 = bias[cb + 1];
                {
                    const float4 xv = *(const float4*)(xin + (size_t)r * 2 * HALF_DIM + 2 * cb);
                    float4 yv;
                    yv.x = xv.x + acc[mt][nt][0] + b0;
                    yv.y = xv.y;
                    yv.z = xv.z + acc[mt][nt][1] + b1;
                    yv.w = xv.w;
                    *(float4*)(yout + (size_t)r * 2 * HALF_DIM + 2 * cb) = yv;
                }
                {
                    const float4 xv = *(const float4*)(xin + (size_t)(r + 8) * 2 * HALF_DIM + 2 * cb);
                    float4 yv;
                    yv.x = xv.x + acc[mt][nt][2] + b0;
                    yv.y = xv.y;
                    yv.z = xv.z + acc[mt][nt][3] + b1;
                    yv.w = xv.w;
                    *(float4*)(yout + (size_t)(r + 8) * 2 * HALF_DIM + 2 * cb) = yv;
                }
            }
        }
    }
}

// ---------------- host ----------------
extern "C" void kernel_launch(void* const* d_in, const int* in_sizes, int n_in,
                              void* d_out, int out_size) {
    const float* x     = (const float*)d_in[0];
    const float* ldj   = (const float*)d_in[1];
    const float* W_in  = (const float*)d_in[2];
    const float* b_in  = (const float*)d_in[3];
    const float* W_h   = (const float*)d_in[4];
    const float* b_h   = (const float*)d_in[5];
    const float* W_out = (const float*)d_in[6];
    const float* b_out = (const float*)d_in[7];
    float* y = (float*)d_out;
    (void)in_sizes; (void)n_in;

    __nv_bfloat16 *px2, *ph0, *ph1, *pwt;
    cudaGetSymbolAddress((void**)&px2, g_x2);
    cudaGetSymbolAddress((void**)&ph0, g_h0);
    cudaGetSymbolAddress((void**)&ph1, g_h1);
    cudaGetSymbolAddress((void**)&pwt, g_wt);

    cudaFuncSetAttribute(gemm_bf16, cudaFuncAttributeMaxDynamicSharedMemorySize, GEMM_SMEM);

    const size_t OFF_WIN  = 0;
    const size_t OFF_WH   = (size_t)HALF_DIM * MID_DIM;
    const size_t OFF_WOUT = OFF_WH + (size_t)NH * MID_DIM * MID_DIM;

    int write_ldj = (out_size > B_ROWS * 2 * HALF_DIM) ? 1 : 0;
    prep_x2<<<(B_ROWS * HALF_DIM) / 256, 256>>>(x, ldj, px2, y, write_ldj);

    // layout-preserving weight converts (fp32 -> bf16)
    convert_bf16<<<(HALF_DIM * MID_DIM) / 1024, 256>>>(W_in, pwt + OFF_WIN);
    convert_bf16<<<(NH * MID_DIM * MID_DIM) / 1024, 256>>>(W_h, pwt + OFF_WH);
    convert_bf16<<<(MID_DIM * HALF_DIM) / 1024, 256>>>(W_out, pwt + OFF_WOUT);

    // L1: h0 = relu(x2 @ W_in + b_in)   [M=4096, N=4096, K=1024]
    gemm_bf16<<<dim3(MID_DIM / TN, B_ROWS / TM), 128, GEMM_SMEM>>>(
        px2, pwt + OFF_WIN, b_in, ph0, nullptr, nullptr,
        HALF_DIM, MID_DIM, HALF_DIM / KC, 0);

    // hidden layers [4096,4096,4096]
    for (int i = 0; i < NH; i++) {
        const __nv_bfloat16* Ain = (i % 2 == 0) ? ph0 : ph1;
        __nv_bfloat16* Cc        = (i % 2 == 0) ? ph1 : ph0;
        gemm_bf16<<<dim3(MID_DIM / TN, B_ROWS / TM), 128, GEMM_SMEM>>>(
            Ain, pwt + OFF_WH + (size_t)i * MID_DIM * MID_DIM,
            b_h + (size_t)i * MID_DIM, Cc, nullptr, nullptr,
            MID_DIM, MID_DIM, MID_DIM / KC, 0);
    }

    // L6: y = interleave(x1 + h @ W_out + b_out, x2)   [M=4096, N=1024, K=4096]
    gemm_bf16<<<dim3(HALF_DIM / TN, B_ROWS / TM), 128, GEMM_SMEM>>>(
        ph0, pwt + OFF_WOUT, b_out, nullptr, x, y,
        MID_DIM, HALF_DIM, MID_DIM / KC, 1);
}

// round 6
// speedup vs baseline: 2.4499x; 1.0002x over previous
#include <cuda_runtime.h>
#include <cuda_bf16.h>
#include <cstdint>

// ---------------- problem constants ----------------
#define B_ROWS   4096
#define HALF_DIM 1024
#define MID_DIM  4096
#define NH       4

// ---------------- scratch (device globals; no cudaMalloc allowed) ----------
__device__ __nv_bfloat16 g_x2[(size_t)B_ROWS * HALF_DIM];            //  8 MB
__device__ __nv_bfloat16 g_h0[(size_t)B_ROWS * MID_DIM];             // 32 MB
__device__ __nv_bfloat16 g_h1[(size_t)B_ROWS * MID_DIM];             // 32 MB
__device__ __nv_bfloat16 g_wt[(size_t)HALF_DIM * MID_DIM +
                              (size_t)NH * MID_DIM * MID_DIM +
                              (size_t)MID_DIM * HALF_DIM];           // 151 MB ([K,N] layout)

// ---------------- helpers ----------------
__device__ __forceinline__ uint32_t smem_u32(const void* p) {
    uint32_t a;
    asm("{ .reg .u64 t; cvta.to.shared.u64 t, %1; cvt.u32.u64 %0, t; }"
        : "=r"(a) : "l"(p));
    return a;
}

#define CP_ASYNC16(dst_u32, src_ptr) \
    asm volatile("cp.async.cg.shared.global [%0], [%1], 16;" \
        :: "r"(dst_u32), "l"(src_ptr) : "memory")
#define CP_COMMIT() asm volatile("cp.async.commit_group;" ::: "memory")
#define CP_WAIT1()  asm volatile("cp.async.wait_group 1;"  ::: "memory")
#define CP_WAIT0()  asm volatile("cp.async.wait_group 0;"  ::: "memory")

#define LDSM_X4(r0, r1, r2, r3, addr) \
    asm volatile("ldmatrix.sync.aligned.m8n8.x4.shared.b16 {%0,%1,%2,%3}, [%4];" \
        : "=r"(r0), "=r"(r1), "=r"(r2), "=r"(r3) : "r"(addr))

#define LDSM_X4_T(r0, r1, r2, r3, addr) \
    asm volatile("ldmatrix.sync.aligned.m8n8.x4.trans.shared.b16 {%0,%1,%2,%3}, [%4];" \
        : "=r"(r0), "=r"(r1), "=r"(r2), "=r"(r3) : "r"(addr))

__device__ __forceinline__ void mma_bf16(float* d, const uint32_t* a, const uint32_t* b) {
    asm volatile(
        "mma.sync.aligned.m16n8k16.row.col.f32.bf16.bf16.f32 "
        "{%0,%1,%2,%3}, {%4,%5,%6,%7}, {%8,%9}, {%0,%1,%2,%3};"
        : "+f"(d[0]), "+f"(d[1]), "+f"(d[2]), "+f"(d[3])
        : "r"(a[0]), "r"(a[1]), "r"(a[2]), "r"(a[3]), "r"(b[0]), "r"(b[1]));
}

// ---------------- prologue kernels ----------------
__global__ void prep_x2(const float* __restrict__ x, const float* __restrict__ ldj,
                        __nv_bfloat16* __restrict__ x2, float* __restrict__ yout,
                        int write_ldj) {
    size_t i = (size_t)blockIdx.x * blockDim.x + threadIdx.x;
    float2 p = ((const float2*)x)[i];
    x2[i] = __float2bfloat16(p.y);
    if (i == 0 && write_ldj) yout[(size_t)B_ROWS * 2 * HALF_DIM] = ldj[0];
}

__global__ void convert_bf16(const float* __restrict__ in, __nv_bfloat16* __restrict__ out) {
    size_t i = (size_t)blockIdx.x * blockDim.x + threadIdx.x;
    float4 v = ((const float4*)in)[i];
    __nv_bfloat162* o = (__nv_bfloat162*)out + 2 * i;
    o[0] = __floats2bfloat162_rn(v.x, v.y);
    o[1] = __floats2bfloat162_rn(v.z, v.w);
}

// ---------------- bf16 mma.sync GEMM ----------------
// C[M,N] = epi( A[M,K] @ W[K,N] + bias ); A K-major bf16, W [K,N] row-major bf16.
// Tile 128x128, KC=64, 3-stage cp.async pipeline, 128 threads (2x2 warps),
// warp tile 64x64; A via ldmatrix, W via ldmatrix.trans.
// Register double-buffered ks pipeline: LDSM for ks+1 issued before MMAs of ks.
#define TM 128
#define TN 128
#define KC 64
#define STAGES 3
#define AROWB 144
#define BROWB 272
#define A_TILE (128 * AROWB)
#define B_TILE (KC * BROWB)
#define STG_BYTES (A_TILE + B_TILE)
#define GEMM_SMEM (STAGES * STG_BYTES)             // 107520

__global__ void __launch_bounds__(128, 2)
gemm_bf16(const __nv_bfloat16* __restrict__ A, const __nv_bfloat16* __restrict__ W,
          const float* __restrict__ bias, __nv_bfloat16* __restrict__ C,
          const float* __restrict__ xin, float* __restrict__ yout,
          int K, int N, int n_chunks, int mode) {
    extern __shared__ char smem[];
    const uint32_t sbase = smem_u32(smem);
    const int tid  = threadIdx.x;
    const int wid  = tid >> 5;
    const int lane = tid & 31;
    const int wm   = wid >> 1;
    const int wn   = wid & 1;
    const int gid  = lane >> 2;
    const int tg   = lane & 3;
    const int m0   = blockIdx.y * TM;
    const int n0   = blockIdx.x * TN;

    const __nv_bfloat16* ag0 = A + (size_t)m0 * K;
    const __nv_bfloat16* bg0 = W + n0;

    const uint32_t a_off = (uint32_t)((wm * 64 + (lane & 15)) * AROWB + (lane >> 4) * 16);
    const int krow = (lane & 7) | (((lane >> 3) & 1) << 3);
    const uint32_t b_off = (uint32_t)(krow * BROWB + wn * 128 + (lane >> 4) * 16);

    auto load_stage = [&](int s, int c) {
        const __nv_bfloat16* ag = ag0 + (size_t)c * KC;
        const __nv_bfloat16* bg = bg0 + (size_t)c * KC * N;
        const uint32_t sa = sbase + (uint32_t)s * STG_BYTES;
        const uint32_t sb = sa + A_TILE;
        #pragma unroll
        for (int i = 0; i < 8; i++) {                 // A: 128 rows x 8 x 16B
            int id  = tid + 128 * i;
            int row = id >> 3, col = id & 7;
            CP_ASYNC16(sa + (uint32_t)(row * AROWB + col * 16),
                       ag + (size_t)row * K + col * 8);
        }
        #pragma unroll
        for (int i = 0; i < 8; i++) {                 // B: 64 rows x 16 x 16B
            int id  = tid + 128 * i;
            int row = id >> 4, col = id & 15;
            CP_ASYNC16(sb + (uint32_t)(row * BROWB + col * 16),
                       bg + (size_t)row * N + col * 8);
        }
        CP_COMMIT();
    };

    float acc[4][8][4];
    #pragma unroll
    for (int i = 0; i < 4; i++)
        #pragma unroll
        for (int j = 0; j < 8; j++)
            #pragma unroll
            for (int v = 0; v < 4; v++) acc[i][j][v] = 0.f;

    load_stage(0, 0);
    load_stage(1, 1);

    uint32_t af[2][4][4], bf[2][4][4];

    int s = 0;
    for (int c = 0; c < n_chunks; c++) {
        CP_WAIT1();
        __syncthreads();
        if (c + 2 < n_chunks) {
            int s2 = s + 2; if (s2 >= STAGES) s2 -= STAGES;
            load_stage(s2, c + 2);
        }
        const uint32_t sa = sbase + (uint32_t)s * STG_BYTES;
        const uint32_t sb = sa + A_TILE;

        // preload fragments for ks = 0
        #pragma unroll
        for (int mt = 0; mt < 4; mt++)
            LDSM_X4(af[0][mt][0], af[0][mt][1], af[0][mt][2], af[0][mt][3],
                    sa + a_off + (uint32_t)(mt * 16 * AROWB));
        #pragma unroll
        for (int np = 0; np < 4; np++)
            LDSM_X4_T(bf[0][np][0], bf[0][np][1], bf[0][np][2], bf[0][np][3],
                      sb + b_off + (uint32_t)(np * 32));

        #pragma unroll
        for (int ks = 0; ks < KC / 16; ks++) {
            const int cur = ks & 1, nxt = cur ^ 1;
            if (ks < KC / 16 - 1) {   // prefetch ks+1 fragments before MMAs of ks
                #pragma unroll
                for (int mt = 0; mt < 4; mt++)
                    LDSM_X4(af[nxt][mt][0], af[nxt][mt][1], af[nxt][mt][2], af[nxt][mt][3],
                            sa + a_off + (uint32_t)(mt * 16 * AROWB + (ks + 1) * 32));
                #pragma unroll
                for (int np = 0; np < 4; np++)
                    LDSM_X4_T(bf[nxt][np][0], bf[nxt][np][1], bf[nxt][np][2], bf[nxt][np][3],
                              sb + b_off + (uint32_t)((ks + 1) * 16 * BROWB + np * 32));
            }
            #pragma unroll
            for (int mt = 0; mt < 4; mt++)
                #pragma unroll
                for (int nt = 0; nt < 8; nt++)
                    mma_bf16(acc[mt][nt], af[cur][mt], &bf[cur][nt >> 1][(nt & 1) * 2]);
        }
        if (++s == STAGES) s = 0;
    }
    CP_WAIT0();

    // ---- epilogue ----
    if (mode == 0) {
        #pragma unroll
        for (int mt = 0; mt < 4; mt++) {
            int r = m0 + wm * 64 + mt * 16 + gid;
            #pragma unroll
            for (int nt = 0; nt < 8; nt++) {
                int cb = n0 + wn * 64 + nt * 8 + 2 * tg;
                float b0 = bias[cb], b1 = bias[cb + 1];
                __nv_bfloat162 v0 = __floats2bfloat162_rn(
                    fmaxf(acc[mt][nt][0] + b0, 0.f), fmaxf(acc[mt][nt][1] + b1, 0.f));
                __nv_bfloat162 v1 = __floats2bfloat162_rn(
                    fmaxf(acc[mt][nt][2] + b0, 0.f), fmaxf(acc[mt][nt][3] + b1, 0.f));
                *(__nv_bfloat162*)(C + (size_t)r * MID_DIM + cb)       = v0;
                *(__nv_bfloat162*)(C + (size_t)(r + 8) * MID_DIM + cb) = v1;
            }
        }
    } else {
        #pragma unroll
        for (int mt = 0; mt < 4; mt++) {
            int r = m0 + wm * 64 + mt * 16 + gid;
            #pragma unroll
            for (int nt = 0; nt < 8; nt++) {
                int cb = n0 + wn * 64 + nt * 8 + 2 * tg;
                float b0 = bias[cb], b1 = bias[cb + 1];
                {
                    const float4 xv = *(const float4*)(xin + (size_t)r * 2 * HALF_DIM + 2 * cb);
                    float4 yv;
                    yv.x = xv.x + acc[mt][nt][0] + b0;
                    yv.y = xv.y;
                    yv.z = xv.z + acc[mt][nt][1] + b1;
                    yv.w = xv.w;
                    *(float4*)(yout + (size_t)r * 2 * HALF_DIM + 2 * cb) = yv;
                }
                {
                    const float4 xv = *(const float4*)(xin + (size_t)(r + 8) * 2 * HALF_DIM + 2 * cb);
                    float4 yv;
                    yv.x = xv.x + acc[mt][nt][2] + b0;
                    yv.y = xv.y;
                    yv.z = xv.z + acc[mt][nt][3] + b1;
                    yv.w = xv.w;
                    *(float4*)(yout + (size_t)(r + 8) * 2 * HALF_DIM + 2 * cb) = yv;
                }
            }
        }
    }
}

// ---------------- host ----------------
extern "C" void kernel_launch(void* const* d_in, const int* in_sizes, int n_in,
                              void* d_out, int out_size) {
    const float* x     = (const float*)d_in[0];
    const float* ldj   = (const float*)d_in[1];
    const float* W_in  = (const float*)d_in[2];
    const float* b_in  = (const float*)d_in[3];
    const float* W_h   = (const float*)d_in[4];
    const float* b_h   = (const float*)d_in[5];
    const float* W_out = (const float*)d_in[6];
    const float* b_out = (const float*)d_in[7];
    float* y = (float*)d_out;
    (void)in_sizes; (void)n_in;

    __nv_bfloat16 *px2, *ph0, *ph1, *pwt;
    cudaGetSymbolAddress((void**)&px2, g_x2);
    cudaGetSymbolAddress((void**)&ph0, g_h0);
    cudaGetSymbolAddress((void**)&ph1, g_h1);
    cudaGetSymbolAddress((void**)&pwt, g_wt);

    cudaFuncSetAttribute(gemm_bf16, cudaFuncAttributeMaxDynamicSharedMemorySize, GEMM_SMEM);

    const size_t OFF_WIN  = 0;
    const size_t OFF_WH   = (size_t)HALF_DIM * MID_DIM;
    const size_t OFF_WOUT = OFF_WH + (size_t)NH * MID_DIM * MID_DIM;

    int write_ldj = (out_size > B_ROWS * 2 * HALF_DIM) ? 1 : 0;
    prep_x2<<<(B_ROWS * HALF_DIM) / 256, 256>>>(x, ldj, px2, y, write_ldj);

    convert_bf16<<<(HALF_DIM * MID_DIM) / 1024, 256>>>(W_in, pwt + OFF_WIN);
    convert_bf16<<<(NH * MID_DIM * MID_DIM) / 1024, 256>>>(W_h, pwt + OFF_WH);
    convert_bf16<<<(MID_DIM * HALF_DIM) / 1024, 256>>>(W_out, pwt + OFF_WOUT);

    // L1: h0 = relu(x2 @ W_in + b_in)   [M=4096, N=4096, K=1024]
    gemm_bf16<<<dim3(MID_DIM / TN, B_ROWS / TM), 128, GEMM_SMEM>>>(
        px2, pwt + OFF_WIN, b_in, ph0, nullptr, nullptr,
        HALF_DIM, MID_DIM, HALF_DIM / KC, 0);

    // hidden layers [4096,4096,4096]
    for (int i = 0; i < NH; i++) {
        const __nv_bfloat16* Ain = (i % 2 == 0) ? ph0 : ph1;
        __nv_bfloat16* Cc        = (i % 2 == 0) ? ph1 : ph0;
        gemm_bf16<<<dim3(MID_DIM / TN, B_ROWS / TM), 128, GEMM_SMEM>>>(
            Ain, pwt + OFF_WH + (size_t)i * MID_DIM * MID_DIM,
            b_h + (size_t)i * MID_DIM, Cc, nullptr, nullptr,
            MID_DIM, MID_DIM, MID_DIM / KC, 0);
    }

    // L6: y = interleave(x1 + h @ W_out + b_out, x2)   [M=4096, N=1024, K=4096]
    gemm_bf16<<<dim3(HALF_DIM / TN, B_ROWS / TM), 128, GEMM_SMEM>>>(
        ph0, pwt + OFF_WOUT, b_out, nullptr, x, y,
        MID_DIM, HALF_DIM, MID_DIM / KC, 1);
}